// round 1
// baseline (speedup 1.0000x reference)
#include <cuda_runtime.h>

#define B   64
#define NR  16384
#define IC  16
#define NC  10
#define OC  16
#define CO  (NC*OC)          // 160
#define SPLITK 32
#define KCH (NR/SPLITK)      // 512
#define KB  32

// Scratch (device globals: no allocations allowed)
__device__ float g_xt[(size_t)IC*B*NR];              // x transposed: [i][b][r]  (67 MB)
__device__ float g_part[(size_t)SPLITK*B*IC*CO];     // split-K partials        (21 MB)
__device__ float g_uhat[B*IC*CO];                    // u_hat [b][i][c*16+o]
__device__ float g_bij[IC*NC];                       // routing logits
__device__ float g_v[B*CO];                          // v_j [b][c*16+o]

// ---- packed f32x2 helpers (sm_103a: fma.rn.f32x2 doubles FFMA throughput) ----
static __device__ __forceinline__ unsigned long long dup2(float v) {
    unsigned long long r;
    asm("mov.b64 %0, {%1, %1};" : "=l"(r) : "f"(v));
    return r;
}
static __device__ __forceinline__ void ffma2(unsigned long long& d,
                                             unsigned long long a,
                                             unsigned long long b) {
    asm("fma.rn.f32x2 %0, %1, %2, %0;" : "+l"(d) : "l"(a), "l"(b));
}
static __device__ __forceinline__ float2 unpk(unsigned long long v) {
    float lo, hi;
    asm("mov.b64 {%0, %1}, %2;" : "=f"(lo), "=f"(hi) : "l"(v));
    return make_float2(lo, hi);
}

// ---------------------------------------------------------------------------
// 1) Transpose x[b][r][i] -> xt[i][b][r]  (both sides coalesced via smem tile)
// grid: (NR/256, B), block: 256
// ---------------------------------------------------------------------------
__global__ void k_transpose(const float* __restrict__ x) {
    __shared__ float tile[16][64];
    const int b   = blockIdx.y;
    const int tid = threadIdx.x;
    const int r   = tid >> 2;            // 0..63
    const int i4  = (tid & 3) * 4;       // 0,4,8,12
    const int i   = tid >> 4;            // 0..15
    const int rs  = (tid & 15) * 4;      // 0..60

    for (int tt = 0; tt < 4; tt++) {
        const int r0 = (blockIdx.x * 4 + tt) * 64;
        float4 v = *(const float4*)(x + ((size_t)b * NR + r0 + r) * IC + i4);
        tile[i4 + 0][r] = v.x;
        tile[i4 + 1][r] = v.y;
        tile[i4 + 2][r] = v.z;
        tile[i4 + 3][r] = v.w;
        __syncthreads();
        float4 o = *(const float4*)&tile[i][rs];
        *(float4*)(g_xt + ((size_t)i * B + b) * NR + r0 + rs) = o;
        __syncthreads();
    }
}

// ---------------------------------------------------------------------------
// 2) Split-K GEMM: per i, C[64,160] += X_i[64, Kchunk] * W_i[160, Kchunk]^T
// grid: (SPLITK, IC), block 256. Thread tile: 4 b-rows x 10 co-cols,
// accumulated as f32x2 pairs along co (5 pairs x 4 rows = 20 packed accs).
// ---------------------------------------------------------------------------
__global__ __launch_bounds__(256) void k_gemm(const float* __restrict__ Wt) {
    __shared__ float xs[KB][68];     // padded vs bank conflicts
    __shared__ float ws[KB][164];

    const int i   = blockIdx.y;
    const int r0  = blockIdx.x * KCH;
    const int tid = threadIdx.x;
    const int tm  = tid & 15;        // b group  (b = tm*4 + bb)
    const int tn  = tid >> 4;        // co group (co = tn*10 + j)

    const float* Wi = Wt  + (size_t)i * CO * NR;
    const float* Xi = g_xt + (size_t)i * B  * NR;

    unsigned long long acc[4][5];
#pragma unroll
    for (int a = 0; a < 4; a++)
#pragma unroll
        for (int p = 0; p < 5; p++) acc[a][p] = 0ull;

    const int xb = tid >> 2;          // 0..63
    const int xk = (tid & 3) * 8;     // 0,8,16,24
    const int wc = tid >> 3;          // 0..31
    const int wk = (tid & 7) * 4;     // 0..28

    for (int kt = 0; kt < KCH; kt += KB) {
        // global loads into regs (overlap with previous compute before sync)
        const float* px = Xi + (size_t)xb * NR + r0 + kt + xk;
        float4 a0 = *(const float4*)px;
        float4 a1 = *(const float4*)(px + 4);
        float4 wf[5];
#pragma unroll
        for (int g = 0; g < 5; g++)
            wf[g] = *(const float4*)(Wi + (size_t)(g * 32 + wc) * NR + r0 + kt + wk);

        __syncthreads();
        xs[xk + 0][xb] = a0.x; xs[xk + 1][xb] = a0.y;
        xs[xk + 2][xb] = a0.z; xs[xk + 3][xb] = a0.w;
        xs[xk + 4][xb] = a1.x; xs[xk + 5][xb] = a1.y;
        xs[xk + 6][xb] = a1.z; xs[xk + 7][xb] = a1.w;
#pragma unroll
        for (int g = 0; g < 5; g++) {
            const int co = g * 32 + wc;
            ws[wk + 0][co] = wf[g].x; ws[wk + 1][co] = wf[g].y;
            ws[wk + 2][co] = wf[g].z; ws[wk + 3][co] = wf[g].w;
        }
        __syncthreads();

#pragma unroll
        for (int k = 0; k < KB; k++) {
            float4 xv = *(const float4*)&xs[k][tm * 4];
            unsigned long long xd0 = dup2(xv.x), xd1 = dup2(xv.y);
            unsigned long long xd2 = dup2(xv.z), xd3 = dup2(xv.w);
            const unsigned long long* wp =
                (const unsigned long long*)&ws[k][tn * 10];
#pragma unroll
            for (int p = 0; p < 5; p++) {
                unsigned long long wv = wp[p];
                ffma2(acc[0][p], xd0, wv);
                ffma2(acc[1][p], xd1, wv);
                ffma2(acc[2][p], xd2, wv);
                ffma2(acc[3][p], xd3, wv);
            }
        }
    }

    // deterministic epilogue: per-chunk partial buffer (no fp32 atomics)
    float* dst = g_part + (size_t)blockIdx.x * (B * IC * CO);
#pragma unroll
    for (int bb = 0; bb < 4; bb++) {
        const int b = tm * 4 + bb;
        float* row = dst + ((size_t)b * IC + i) * CO + tn * 10;
#pragma unroll
        for (int p = 0; p < 5; p++) {
            float2 f = unpk(acc[bb][p]);
            *(float2*)&row[2 * p] = f;
        }
    }
}

// ---------------------------------------------------------------------------
// 3) Reduce split-K partials -> g_uhat; also zero routing logits.
// grid: (B*IC*CO)/256 = 640, block 256
// ---------------------------------------------------------------------------
__global__ void k_reduce() {
    const int idx = blockIdx.x * blockDim.x + threadIdx.x;
    float s = 0.f;
#pragma unroll
    for (int c = 0; c < SPLITK; c++)
        s += g_part[(size_t)c * (B * IC * CO) + idx];
    g_uhat[idx] = s;
    if (idx < IC * NC) g_bij[idx] = 0.f;
}

// ---------------------------------------------------------------------------
// 4) Routing step: c = softmax_i(b_ij) (max-subtracted: b_ij grows to ~1e2),
//    s[b,c,o] = sum_i c[i,c]*u_hat[b,i,c,o], v = squash(s) = s*|s|/(1+s^2)
// grid: B, block: 160 (t = c*16 + o)
// ---------------------------------------------------------------------------
__global__ void k_route() {
    __shared__ float csh[IC * NC];
    const int b = blockIdx.x, t = threadIdx.x;
    if (t < NC) {
        float m = -1e30f;
#pragma unroll
        for (int i = 0; i < IC; i++) m = fmaxf(m, g_bij[i * NC + t]);
        float e[IC], sum = 0.f;
#pragma unroll
        for (int i = 0; i < IC; i++) {
            e[i] = expf(g_bij[i * NC + t] - m);
            sum += e[i];
        }
        const float inv = 1.f / sum;
#pragma unroll
        for (int i = 0; i < IC; i++) csh[i * NC + t] = e[i] * inv;
    }
    __syncthreads();
    const int c = t >> 4;
    const float* u = g_uhat + (size_t)b * IC * CO + t;
    float s = 0.f;
#pragma unroll
    for (int i = 0; i < IC; i++) s += csh[i * NC + c] * u[i * CO];
    const float v = s * fabsf(s) / (1.f + s * s);
    g_v[b * CO + t] = v;
}

// ---------------------------------------------------------------------------
// 5) Agreement: b_ij[i,c] += (1/B) * sum_{b,o} u_hat[b,i,c,o]*v[b,c,o]
// grid: IC*NC = 160, block: 64 (one per batch)
// ---------------------------------------------------------------------------
__global__ void k_agree() {
    const int ic = blockIdx.x;
    const int i = ic / NC, c = ic % NC;
    const int b = threadIdx.x;
    const float4* u = (const float4*)(g_uhat + ((size_t)b * IC + i) * CO + c * OC);
    const float4* v = (const float4*)(g_v + (size_t)b * CO + c * OC);
    float s = 0.f;
#pragma unroll
    for (int q = 0; q < 4; q++) {
        float4 uu = u[q], vv = v[q];
        s += uu.x * vv.x + uu.y * vv.y + uu.z * vv.z + uu.w * vv.w;
    }
    for (int off = 16; off; off >>= 1) s += __shfl_down_sync(0xffffffffu, s, off);
    __shared__ float red[2];
    if ((b & 31) == 0) red[b >> 5] = s;
    __syncthreads();
    if (b == 0) g_bij[ic] += (red[0] + red[1]) * (1.0f / B);
}

// ---------------------------------------------------------------------------
// 6) Final: out[0:64] = sigmoid(v . fc_w + fc_b), out[64:] = v_j (b,c,o order)
// grid: B, block: 160
// ---------------------------------------------------------------------------
__global__ void k_final(const float* __restrict__ fcw,
                        const float* __restrict__ fcb,
                        float* __restrict__ out) {
    const int b = blockIdx.x, t = threadIdx.x;
    const float v = g_v[b * CO + t];
    out[B + b * CO + t] = v;
    float p = v * fcw[t];
    for (int off = 16; off; off >>= 1) p += __shfl_down_sync(0xffffffffu, p, off);
    __shared__ float red[5];
    if ((t & 31) == 0) red[t >> 5] = p;
    __syncthreads();
    if (t == 0) {
        const float s = red[0] + red[1] + red[2] + red[3] + red[4] + fcb[0];
        out[b] = 1.f / (1.f + expf(-s));
    }
}

// ---------------------------------------------------------------------------
extern "C" void kernel_launch(void* const* d_in, const int* in_sizes, int n_in,
                              void* d_out, int out_size) {
    const float* x   = (const float*)d_in[0];
    const float* W   = (const float*)d_in[1];
    const float* fcw = (const float*)d_in[2];
    const float* fcb = (const float*)d_in[3];
    float* out = (float*)d_out;

    k_transpose<<<dim3(NR / 256, B), 256>>>(x);
    k_gemm<<<dim3(SPLITK, IC), 256>>>(W);
    k_reduce<<<(B * IC * CO) / 256, 256>>>();
    for (int it = 0; it < 3; it++) {
        k_route<<<B, CO>>>();
        if (it < 2) k_agree<<<IC * NC, B>>>();
    }
    k_final<<<B, CO>>>(fcw, fcb, out);
}

// round 3
// speedup vs baseline: 1.9635x; 1.9635x over previous
#include <cuda_runtime.h>
#include <cuda_bf16.h>
#include <cstdint>

#define B_   64
#define NR_  16384
#define IC_  16
#define NC_  10
#define OC_  16
#define CO_  160
#define SPLITK 16
#define KCH  (NR_/SPLITK)   // 1024
#define KB   32
#define NCH  (KCH/KB)       // 32

// -------- device scratch (no allocations allowed) --------
__device__ __nv_bfloat16 g_xhi[(size_t)IC_*B_*NR_];     // x hi  [i][b][r]
__device__ __nv_bfloat16 g_xlo[(size_t)IC_*B_*NR_];     // x lo  [i][b][r]
__device__ float g_part[(size_t)SPLITK*B_*IC_*CO_];     // split-K partials
__device__ float g_uhat[B_*IC_*CO_];                    // u_hat [b][i][co]
__device__ float g_v   [B_*CO_];                        // v_j [b][co]

// smem layout (bytes): W rows padded to 40 halves (80B) for bank-conflict-free
// fragment loads.  W stage = 160*40 halves = 12800B, x stage = 64*40 = 5120B.
#define OFF_WHI 0
#define OFF_WLO 25600
#define OFF_XHI 51200
#define OFF_XLO 61440
#define SMEM_T  71680

static __device__ __forceinline__ void bsplit(float v, __nv_bfloat16& h,
                                              __nv_bfloat16& l) {
    h = __float2bfloat16(v);
    l = __float2bfloat16(v - __bfloat162float(h));
}

static __device__ __forceinline__ void mma16816(float* c, const uint32_t* a,
                                                const uint32_t* b) {
    asm volatile(
        "mma.sync.aligned.m16n8k16.row.col.f32.bf16.bf16.f32 "
        "{%0,%1,%2,%3}, {%4,%5,%6,%7}, {%8,%9}, {%0,%1,%2,%3};"
        : "+f"(c[0]), "+f"(c[1]), "+f"(c[2]), "+f"(c[3])
        : "r"(a[0]), "r"(a[1]), "r"(a[2]), "r"(a[3]), "r"(b[0]), "r"(b[1]));
}

// ---------------------------------------------------------------------------
// 1) Transpose + bf16 split: x[b][r][i] -> xhi/xlo [i][b][r]
// ---------------------------------------------------------------------------
__global__ void k_transpose(const float* __restrict__ x) {
    __shared__ float tile[16][64];
    const int b = blockIdx.y, tid = threadIdx.x;
    const int r = tid >> 2, i4 = (tid & 3) * 4;
    const int i = tid >> 4, rs = (tid & 15) * 4;
    for (int tt = 0; tt < 4; tt++) {
        const int r0 = (blockIdx.x * 4 + tt) * 64;
        float4 v = *(const float4*)(x + ((size_t)b * NR_ + r0 + r) * IC_ + i4);
        tile[i4 + 0][r] = v.x; tile[i4 + 1][r] = v.y;
        tile[i4 + 2][r] = v.z; tile[i4 + 3][r] = v.w;
        __syncthreads();
        float4 o = *(const float4*)&tile[i][rs];
        union { __nv_bfloat16 h[4]; uint2 u; } ph, pl;
        bsplit(o.x, ph.h[0], pl.h[0]);
        bsplit(o.y, ph.h[1], pl.h[1]);
        bsplit(o.z, ph.h[2], pl.h[2]);
        bsplit(o.w, ph.h[3], pl.h[3]);
        const size_t dst = ((size_t)i * B_ + b) * NR_ + r0 + rs;
        *(uint2*)(g_xhi + dst) = ph.u;
        *(uint2*)(g_xlo + dst) = pl.u;
        __syncthreads();
    }
}

// ---------------------------------------------------------------------------
// 2) bf16x3 HMMA GEMM. grid (SPLITK, IC), 256 threads (8 warps, 2m x 4n).
//    CTA computes C[160 co, 64 b] over K=1024, KB=32 double-buffered.
// ---------------------------------------------------------------------------
__global__ __launch_bounds__(256, 2) void k_gemm(const float* __restrict__ Wg) {
    extern __shared__ char smem[];
    __nv_bfloat16* swh = (__nv_bfloat16*)(smem + OFF_WHI);
    __nv_bfloat16* swl = (__nv_bfloat16*)(smem + OFF_WLO);
    __nv_bfloat16* sxh = (__nv_bfloat16*)(smem + OFF_XHI);
    __nv_bfloat16* sxl = (__nv_bfloat16*)(smem + OFF_XLO);

    const int i = blockIdx.y, split = blockIdx.x, t = threadIdx.x;
    const int warp = t >> 5, lane = t & 31;
    const int wm = warp >> 2, wn = warp & 3;     // warp tile: m 80, n 16
    const int r0 = split * KCH;
    const float* Wi = Wg + (size_t)i * CO_ * NR_;
    const __nv_bfloat16* Xh = g_xhi + (size_t)i * B_ * NR_;
    const __nv_bfloat16* Xl = g_xlo + (size_t)i * B_ * NR_;

    float acc[5][2][4];
#pragma unroll
    for (int m = 0; m < 5; m++)
#pragma unroll
        for (int n = 0; n < 2; n++)
#pragma unroll
            for (int q = 0; q < 4; q++) acc[m][n][q] = 0.f;

    // staging registers
    float4 wr[5];
    uint4 xh, xl;
    const int wrow = t >> 3, wk4 = t & 7;        // W: 5 strided float4 each
    const int xrow = t >> 2, xk8 = (t & 3) * 8;  // x: one uint4 each (8 halves)

#define LOADG(nn) {                                                          \
        const float* wp = Wi + (size_t)wrow * NR_ + r0 + (nn) * KB + wk4*4;  \
        _Pragma("unroll")                                                    \
        for (int q = 0; q < 5; q++) wr[q] = *(const float4*)(wp + (size_t)q*32*NR_); \
        const size_t xo = (size_t)xrow * NR_ + r0 + (nn) * KB + xk8;         \
        xh = *(const uint4*)(Xh + xo);                                       \
        xl = *(const uint4*)(Xl + xo); }

#define STS(ss) {                                                            \
        _Pragma("unroll")                                                    \
        for (int q = 0; q < 5; q++) {                                        \
            union { __nv_bfloat16 h[4]; uint2 u; } ph, pl;                   \
            bsplit(wr[q].x, ph.h[0], pl.h[0]);                               \
            bsplit(wr[q].y, ph.h[1], pl.h[1]);                               \
            bsplit(wr[q].z, ph.h[2], pl.h[2]);                               \
            bsplit(wr[q].w, ph.h[3], pl.h[3]);                               \
            const int so = (ss) * 6400 + (wrow + q * 32) * 40 + wk4 * 4;     \
            *(uint2*)(swh + so) = ph.u;                                      \
            *(uint2*)(swl + so) = pl.u;                                      \
        }                                                                    \
        const int xs = (ss) * 2560 + xrow * 40 + xk8;                        \
        *(uint4*)(sxh + xs) = xh;                                            \
        *(uint4*)(sxl + xs) = xl; }

    LOADG(0);
    STS(0);
    __syncthreads();

    for (int n = 0; n < NCH; n++) {
        const int s = n & 1;
        if (n + 1 < NCH) LOADG(n + 1);

        const __nv_bfloat16* wh = swh + s * 6400;
        const __nv_bfloat16* wl = swl + s * 6400;
        const __nv_bfloat16* xhs = sxh + s * 2560;
        const __nv_bfloat16* xls = sxl + s * 2560;
#pragma unroll
        for (int kb = 0; kb < 2; kb++) {
            const int kc = kb * 16 + (lane & 3) * 2;
            uint32_t bh[2][2], bl[2][2];
#pragma unroll
            for (int nf = 0; nf < 2; nf++) {
                const int col = wn * 16 + nf * 8 + (lane >> 2);
                const __nv_bfloat16* p = xhs + col * 40 + kc;
                const __nv_bfloat16* q = xls + col * 40 + kc;
                bh[nf][0] = *(const uint32_t*)p;
                bh[nf][1] = *(const uint32_t*)(p + 8);
                bl[nf][0] = *(const uint32_t*)q;
                bl[nf][1] = *(const uint32_t*)(q + 8);
            }
#pragma unroll
            for (int m = 0; m < 5; m++) {
                const int row = wm * 80 + m * 16 + (lane >> 2);
                const __nv_bfloat16* p = wh + row * 40 + kc;
                const __nv_bfloat16* q = wl + row * 40 + kc;
                uint32_t ah[4], al[4];
                ah[0] = *(const uint32_t*)p;
                ah[1] = *(const uint32_t*)(p + 320);
                ah[2] = *(const uint32_t*)(p + 8);
                ah[3] = *(const uint32_t*)(p + 328);
                al[0] = *(const uint32_t*)q;
                al[1] = *(const uint32_t*)(q + 320);
                al[2] = *(const uint32_t*)(q + 8);
                al[3] = *(const uint32_t*)(q + 328);
#pragma unroll
                for (int nf = 0; nf < 2; nf++) {
                    mma16816(acc[m][nf], ah, bh[nf]);
                    mma16816(acc[m][nf], ah, bl[nf]);
                    mma16816(acc[m][nf], al, bh[nf]);
                }
            }
        }
        __syncthreads();
        if (n + 1 < NCH) {
            STS(s ^ 1);
            __syncthreads();
        }
    }

    // epilogue: scatter fp32 partials (deterministic split-K buffer)
    float* base = g_part + (size_t)split * (B_ * IC_ * CO_);
#pragma unroll
    for (int m = 0; m < 5; m++) {
        const int co = wm * 80 + m * 16 + (lane >> 2);
#pragma unroll
        for (int nf = 0; nf < 2; nf++) {
            const int bc = wn * 16 + nf * 8 + (lane & 3) * 2;
            float* d = base + ((size_t)bc * IC_ + i) * CO_ + co;
            d[0]        = acc[m][nf][0];
            d[2560]     = acc[m][nf][1];   // b+1
            d[8]        = acc[m][nf][2];   // co+8
            d[2568]     = acc[m][nf][3];
        }
    }
}

// ---------------------------------------------------------------------------
// 3) Reduce split-K partials -> g_uhat
// ---------------------------------------------------------------------------
__global__ void k_reduce() {
    const int idx = blockIdx.x * blockDim.x + threadIdx.x;
    float s = 0.f;
#pragma unroll
    for (int c = 0; c < SPLITK; c++)
        s += g_part[(size_t)c * (B_ * IC_ * CO_) + idx];
    g_uhat[idx] = s;
}

// ---------------------------------------------------------------------------
// 4) Full routing (3 iterations) fused: one CTA per capsule c.
// ---------------------------------------------------------------------------
__global__ __launch_bounds__(512) void k_route_all(float* __restrict__ out) {
    extern __shared__ float sm[];
    float* u_s  = sm;             // [16][64][16]
    float* v_s  = sm + 16384;     // [1024]
    float* csh  = sm + 17408;     // [16]
    float* bijs = sm + 17424;     // [16]
    const int c = blockIdx.x, t = threadIdx.x;

    for (int f = t; f < 4096; f += 512) {
        int o4 = f & 3, b = (f >> 2) & 63, i = f >> 8;
        float4 v = *(const float4*)(g_uhat + ((size_t)(b * IC_ + i)) * CO_
                                    + c * OC_ + o4 * 4);
        *(float4*)(u_s + (i * 64 + b) * 16 + o4 * 4) = v;
    }
    if (t < 16) bijs[t] = 0.f;
    __syncthreads();

    for (int it = 0; it < 3; it++) {
        if (t < 32) {
            float bv = (t < 16) ? bijs[t] : -1e30f;
            float m = bv;
#pragma unroll
            for (int off = 8; off; off >>= 1)
                m = fmaxf(m, __shfl_xor_sync(0xffffffffu, m, off, 16));
            float e = expf(bv - m), sum = e;
#pragma unroll
            for (int off = 8; off; off >>= 1)
                sum += __shfl_xor_sync(0xffffffffu, sum, off, 16);
            if (t < 16) csh[t] = e / sum;
        }
        __syncthreads();
        for (int p = t; p < 1024; p += 512) {
            float s = 0.f;
#pragma unroll
            for (int i = 0; i < IC_; i++) s += csh[i] * u_s[i * 1024 + p];
            v_s[p] = s * fabsf(s) / (1.f + s * s);
        }
        __syncthreads();
        if (it < 2) {
            const int i = t >> 5, l = t & 31;
            float a = 0.f;
            for (int j = l; j < 1024; j += 32) a += u_s[i * 1024 + j] * v_s[j];
#pragma unroll
            for (int off = 16; off; off >>= 1)
                a += __shfl_down_sync(0xffffffffu, a, off);
            if (l == 0) bijs[i] += a * (1.0f / B_);
            __syncthreads();
        }
    }
    for (int p = t; p < 1024; p += 512) {
        const int b = p >> 4, o = p & 15;
        const float v = v_s[p];
        g_v[b * CO_ + c * OC_ + o] = v;
        out[B_ + b * CO_ + c * OC_ + o] = v;
    }
}

// ---------------------------------------------------------------------------
// 5) pred = sigmoid(v . fc_w + fc_b)
// ---------------------------------------------------------------------------
__global__ void k_final(const float* __restrict__ fcw,
                        const float* __restrict__ fcb,
                        float* __restrict__ out) {
    const int b = blockIdx.x, t = threadIdx.x;
    float p = g_v[b * CO_ + t] * fcw[t];
#pragma unroll
    for (int off = 16; off; off >>= 1) p += __shfl_down_sync(0xffffffffu, p, off);
    __shared__ float red[5];
    if ((t & 31) == 0) red[t >> 5] = p;
    __syncthreads();
    if (t == 0) {
        const float s = red[0] + red[1] + red[2] + red[3] + red[4] + fcb[0];
        out[b] = 1.f / (1.f + expf(-s));
    }
}

// ---------------------------------------------------------------------------
extern "C" void kernel_launch(void* const* d_in, const int* in_sizes, int n_in,
                              void* d_out, int out_size) {
    const float* x   = (const float*)d_in[0];
    const float* W   = (const float*)d_in[1];
    const float* fcw = (const float*)d_in[2];
    const float* fcb = (const float*)d_in[3];
    float* out = (float*)d_out;

    cudaFuncSetAttribute(k_gemm, cudaFuncAttributeMaxDynamicSharedMemorySize, SMEM_T);
    cudaFuncSetAttribute(k_route_all, cudaFuncAttributeMaxDynamicSharedMemorySize, 70144);

    k_transpose<<<dim3(NR_ / 256, B_), 256>>>(x);
    k_gemm<<<dim3(SPLITK, IC_), 256, SMEM_T>>>(W);
    k_reduce<<<(B_ * IC_ * CO_) / 256, 256>>>();
    k_route_all<<<NC_, 512, 70144>>>(out);
    k_final<<<B_, CO_>>>(fcw, fcb, out);
}